// round 15
// baseline (speedup 1.0000x reference)
#include <cuda_runtime.h>
#include <math.h>

#define NS 131072
#define LE 100
#define LD 50
#define HD 200
#define SPD 202
#define BT 64
#define THREADS 256
#define HP 204
#define Y1P 104
#define Y2P 52
#define TP 224
#define TP2 112

typedef unsigned long long ull;

__device__ float gruT[25 * 24 * 224];
__device__ float d1T[100 * 224];
__device__ float d2T[50 * 112];

__device__ __forceinline__ ull fma2(ull a, ull b, ull c) {
    ull d;
    asm("fma.rn.f32x2 %0, %1, %2, %3;" : "=l"(d) : "l"(a), "l"(b), "l"(c));
    return d;
}
__device__ __forceinline__ float red2(ull v) {
    float lo, hi;
    asm("mov.b64 {%0, %1}, %2;" : "=f"(lo), "=f"(hi) : "l"(v));
    return lo + hi;
}
__device__ __forceinline__ ull pk(float lo, float hi) {
    ull r;
    asm("mov.b64 %0, {%1, %2};" : "=l"(r) : "f"(lo), "f"(hi));
    return r;
}
__device__ __forceinline__ unsigned su32(const void* p) {
    return (unsigned)__cvta_generic_to_shared(p);
}
__device__ __forceinline__ void cpa16(unsigned dst, const void* src) {
    asm volatile("cp.async.cg.shared.global [%0], [%1], 16;" :: "r"(dst), "l"(src));
}
#define CP_COMMIT() asm volatile("cp.async.commit_group;" ::: "memory")
#define CP_WAIT0()  asm volatile("cp.async.wait_group 0;" ::: "memory")

template <int N2>
__device__ __forceinline__ float dotAB(const float* __restrict__ a, const float* __restrict__ b) {
    const ulonglong2* A2 = (const ulonglong2*)a;
    const ull* B = (const ull*)b;
    ull a0 = 0ull, a1 = 0ull;
#pragma unroll
    for (int i = 0; i < N2 / 2; ++i) {
        ulonglong2 x = A2[i];
        a0 = fma2(x.x, B[2 * i], a0);
        a1 = fma2(x.y, B[2 * i + 1], a1);
    }
    if (N2 & 1) a0 = fma2(((const ull*)a)[N2 - 1], B[N2 - 1], a0);
    return red2(a0) + red2(a1);
}

__device__ __forceinline__ float lrelu(float x) { return x > 0.f ? x : 0.01f * x; }
__device__ __forceinline__ float sigm(float x) {
    return __fdividef(1.0f, 1.0f + __expf(-x));
}
__device__ __forceinline__ float tanh_f(float x) {
    float t = __expf(-2.0f * fabsf(x));
    float r = __fdividef(1.0f - t, 1.0f + t);
    return copysignf(r, x);
}

// smem map (floats)
#define OFF_H    0
#define OFF_Y1   13056
#define OFF_TA   19712
#define OFF_T0   19712
#define OFF_T1   22400
#define OFF_GC   25088
#define OFF_B1   26688
#define OFF_B2   26788
#define OFF_W3   26838
#define OFF_B3   26888
#define OFF_DIN  26892
#define OFF_CT   26956
#define OFF_ST   27056
#define SMEM_FLOATS 27156
#define SMEM_BYTES  (SMEM_FLOATS * 4)

__global__ void prep_kernel(const float* __restrict__ w_hh,
                            const float* __restrict__ dec_w1,
                            const float* __restrict__ dec_w2) {
    int idx = blockIdx.x * blockDim.x + threadIdx.x;
    if (idx < 25 * 24 * 224) {
        int k = idx / (24 * 224);
        int rem = idx - k * (24 * 224);
        int row = rem / 224, col = rem - row * 224;
        int jj = row / 3, g = row - jj * 3;
        int oct = col / 28, c = col - oct * 28;
        float v = 0.f;
        if (c < 25) v = w_hh[(size_t)(g * 200 + k * 8 + jj) * 200 + 25 * oct + c];
        gruT[idx] = v;
        return;
    }
    int idx2 = idx - 25 * 24 * 224;
    if (idx2 < 100 * 224) {
        int row = idx2 / 224, col = idx2 - row * 224;
        int oct = col / 28, c = col - oct * 28;
        d1T[idx2] = (c < 25) ? dec_w1[(size_t)row * 200 + 25 * oct + c] : 0.f;
        return;
    }
    int idx3 = idx2 - 100 * 224;
    if (idx3 < 50 * 112) {
        int row = idx3 / 112, col = idx3 - row * 112;
        int q = col / 28, c = col - q * 28;
        d2T[idx3] = (c < 25) ? dec_w2[(size_t)row * 100 + 25 * q + c] : 0.f;
    }
}

__device__ __forceinline__ void stage_gru_tile(float* buf, int k, int tid) {
    const float4* src = (const float4*)(gruT + k * (24 * 224));
    unsigned d = su32(buf);
#pragma unroll
    for (int rep = 0; rep < 6; ++rep) {
        int i = tid + rep * THREADS;
        if (i < 1344) cpa16(d + i * 16, src + i);
    }
}
__device__ __forceinline__ void stage_d1_tile(float* buf, int r0, int nrows, int tid) {
    const float4* src = (const float4*)(d1T + r0 * 224);
    unsigned d = su32(buf);
    int n = nrows * 56;
#pragma unroll
    for (int rep = 0; rep < 3; ++rep) {
        int i = tid + rep * THREADS;
        if (i < n) cpa16(d + i * 16, src + i);
    }
}
__device__ __forceinline__ void stage_d2_tile(float* buf, int r0, int nrows, int tid) {
    const float4* src = (const float4*)(d2T + r0 * 112);
    unsigned d = su32(buf);
    int n = nrows * 28;
#pragma unroll
    for (int rep = 0; rep < 2; ++rep) {
        int i = tid + rep * THREADS;
        if (i < n) cpa16(d + i * 16, src + i);
    }
}

__global__ void __launch_bounds__(THREADS, 2)
seq2seq_gru_kernel(
    const float* __restrict__ enc_in,
    const float* __restrict__ enc_w1, const float* __restrict__ enc_b1,
    const float* __restrict__ enc_w2, const float* __restrict__ enc_b2,
    const float* __restrict__ enc_wl, const float* __restrict__ enc_bl,
    const float* __restrict__ w_ih,  const float* __restrict__ w_hh,
    const float* __restrict__ b_ih,  const float* __restrict__ b_hh,
    const float* __restrict__ dec_b1, const float* __restrict__ dec_b2,
    const float* __restrict__ dec_w3, const float* __restrict__ dec_b3,
    float* __restrict__ out)
{
    extern __shared__ float sm[];
    float* hbuf = sm + OFF_H;
    float* smY1 = sm + OFF_Y1;
    float* tbA  = sm + OFF_TA;
    float* tb0  = sm + OFF_T0;
    float* tb1  = sm + OFF_T1;
    float* gc   = sm + OFF_GC;
    float* cb1  = sm + OFF_B1;
    float* cb2  = sm + OFF_B2;
    float* w3s  = sm + OFF_W3;
    float* b3s  = sm + OFF_B3;
    float* din  = sm + OFF_DIN;
    float* ctab = sm + OFF_CT;
    float* stab = sm + OFF_ST;

    const int tid  = threadIdx.x;
    const int lane = tid & 31;
    const int w    = tid >> 5;          // 8 warps
    const int cta  = blockIdx.x;
    const float* inbase = enc_in + (size_t)cta * BT * LE;
    float* sig = hbuf;

    for (int idx = tid; idx < BT * LE; idx += THREADS) {
        int s = idx / LE, t = idx - s * LE;
        sig[s * HP + t] = inbase[idx];
    }
    if (tid < 100) {
        float u = (float)tid / 50.0f;
        ctab[tid] = cospif(u);
        stab[tid] = sinpif(u);
    }
    if (tid < BT) din[tid] = inbase[tid * LE + (LE - 1)];
    if (tid < 200) {
        int j = tid;
        gc[j * 8 + 0] = b_ih[j] + b_hh[j];
        gc[j * 8 + 1] = b_ih[HD + j] + b_hh[HD + j];
        gc[j * 8 + 2] = b_hh[2 * HD + j];
        gc[j * 8 + 3] = b_ih[2 * HD + j];
        gc[j * 8 + 4] = w_ih[j];
        gc[j * 8 + 5] = w_ih[HD + j];
        gc[j * 8 + 6] = w_ih[2 * HD + j];
        gc[j * 8 + 7] = 0.f;
    }
    if (tid < 100) cb1[tid] = dec_b1[tid];
    if (tid < 50)  { cb2[tid] = dec_b2[tid]; w3s[tid] = dec_w3[tid]; }
    if (tid == 0)  b3s[0] = dec_b3[0];
    __syncthreads();

    // DFT features (8-warp version)
    for (int kk = 0; kk < 7; ++kk) {
        int k = w + 8 * kk;
        if (k < 51) {
#pragma unroll
            for (int p = 0; p < 2; ++p) {
                int s = lane + 32 * p;
                const float* xr = sig + s * HP;
                float re = 0.f, im = 0.f;
                int m = 0;
                for (int t = 0; t < LE; ++t) {
                    float xv = xr[t];
                    re += xv * ctab[m];
                    im -= xv * stab[m];
                    m += k; if (m >= 100) m -= 100;
                }
                re *= 0.01f; im *= 0.01f;
                if (k == 0 || k == 50) im = 0.0f;
                sig[s * HP + 100 + k] = sqrtf(re * re + im * im);
                sig[s * HP + 151 + k] = atan2f(im, re);
            }
        }
    }
    __syncthreads();

    // encoder L1 [202]->[100]
    {
        float* xbuf = smY1;
        for (int ii = 0; ii < 13; ++ii) {
            int i = w + 8 * ii;
            if (i < 100) {
                float b = enc_b1[i];
                const float* wr = enc_w1 + (size_t)i * SPD;
#pragma unroll
                for (int p = 0; p < 2; ++p) {
                    int s = lane + 32 * p;
                    xbuf[s * 100 + i] = lrelu(dotAB<101>(sig + s * HP, wr) + b);
                }
            }
        }
        __syncthreads();
        // encoder L2 [100]->[202]
        for (int ii = 0; ii < 26; ++ii) {
            int i = w + 8 * ii;
            if (i < SPD) {
                float b = enc_b2[i];
                const float* wr = enc_w2 + (size_t)i * 100;
#pragma unroll
                for (int p = 0; p < 2; ++p) {
                    int s = lane + 32 * p;
                    sig[s * HP + i] = lrelu(dotAB<50>(xbuf + s * 100, wr) + b);
                }
            }
        }
        __syncthreads();
    }
    // encoder final [202]->[200] -> h0 in-place via tmp
    for (int half = 0; half < 2; ++half) {
        float* tmp = smY1;
        for (int ii = 0; ii < 25; ++ii) {
            int i = w + 8 * ii;
            int s = lane + 32 * half;
            tmp[lane * 200 + i] = dotAB<101>(sig + s * HP, enc_wl + (size_t)i * SPD) + enc_bl[i];
        }
        __syncthreads();
        for (int idx = tid; idx < 32 * 200; idx += THREADS) {
            int sp_ = idx / 200, i = idx - sp_ * 200;
            hbuf[(32 * half + sp_) * HP + i] = tmp[idx];
        }
        __syncthreads();
    }

    // decode: 8 warps, lane = oct(8) x sp(4); warp owns samples w*8 .. w*8+7
    const int oct = lane >> 2;
    const int sp  = lane & 3;
    const int sA  = w * 8 + sp;
    const int sB  = sA + 4;
    const int o0 = oct & 1, o1 = (oct >> 1) & 1, o2 = oct >> 2;
    const int s_gru = o0 ? sB : sA;        // GRU combo sample
    const bool wr_h = (o2 == 0);
    const int s_dl1 = o0 ? sB : sA;        // dec L1 writer sample
    const bool wr_y1 = (oct < 2);

    for (int t = 0; t < LD; ++t) {
        ull ha[2][14];
#pragma unroll
        for (int q = 0; q < 2; ++q) {
            const int s = q ? sB : sA;
            float ta[28];
#pragma unroll
            for (int c = 0; c < 25; ++c)
                ta[c] = hbuf[s * HP + 25 * oct + c];
#pragma unroll
            for (int c = 25; c < 28; ++c) ta[c] = 0.f;
#pragma unroll
            for (int c = 0; c < 14; ++c) ha[q][c] = pk(ta[2 * c], ta[2 * c + 1]);
        }
        const float d_eff = din[s_gru];

        // ---- GRU: 25 tiles of 8 j; deferred tails ----
        stage_gru_tile(tbA, 0, tid);
        CP_COMMIT();
        CP_WAIT0();
        __syncthreads();
        float px[3];
        int pjb = -1;
#pragma unroll 1
        for (int k = 0; k < 25; ++k) {
            float* cur = (k & 1) ? smY1 : tbA;
            float* nxt = (k & 1) ? tbA : smY1;
            if (k + 1 < 25) { stage_gru_tile(nxt, k + 1, tid); }
            CP_COMMIT();
            const int j0 = k * 8;
            const float* cur_o = cur + oct * 28;
#pragma unroll 1
            for (int jp = 0; jp < 8; jp += 2) {
                const float* rowp = cur_o + jp * 3 * TP;
                const ulonglong2* W0 = (const ulonglong2*)(rowp + 0 * TP);
                const ulonglong2* W1 = (const ulonglong2*)(rowp + 1 * TP);
                const ulonglong2* W2 = (const ulonglong2*)(rowp + 2 * TP);
                const ulonglong2* W3 = (const ulonglong2*)(rowp + 3 * TP);
                const ulonglong2* W4 = (const ulonglong2*)(rowp + 4 * TP);
                const ulonglong2* W5 = (const ulonglong2*)(rowp + 5 * TP);
                ull acc[6][2];
#pragma unroll
                for (int r = 0; r < 6; ++r) { acc[r][0] = 0ull; acc[r][1] = 0ull; }
#pragma unroll
                for (int c = 0; c < 7; ++c) {
                    ull hx = ha[0][2 * c], hy = ha[0][2 * c + 1];
                    ull gx = ha[1][2 * c], gy = ha[1][2 * c + 1];
                    ulonglong2 wv;
                    wv = W0[c];
                    acc[0][0] = fma2(hx, wv.x, acc[0][0]); acc[0][0] = fma2(hy, wv.y, acc[0][0]);
                    acc[0][1] = fma2(gx, wv.x, acc[0][1]); acc[0][1] = fma2(gy, wv.y, acc[0][1]);
                    wv = W1[c];
                    acc[1][0] = fma2(hx, wv.x, acc[1][0]); acc[1][0] = fma2(hy, wv.y, acc[1][0]);
                    acc[1][1] = fma2(gx, wv.x, acc[1][1]); acc[1][1] = fma2(gy, wv.y, acc[1][1]);
                    wv = W2[c];
                    acc[2][0] = fma2(hx, wv.x, acc[2][0]); acc[2][0] = fma2(hy, wv.y, acc[2][0]);
                    acc[2][1] = fma2(gx, wv.x, acc[2][1]); acc[2][1] = fma2(gy, wv.y, acc[2][1]);
                    wv = W3[c];
                    acc[3][0] = fma2(hx, wv.x, acc[3][0]); acc[3][0] = fma2(hy, wv.y, acc[3][0]);
                    acc[3][1] = fma2(gx, wv.x, acc[3][1]); acc[3][1] = fma2(gy, wv.y, acc[3][1]);
                    wv = W4[c];
                    acc[4][0] = fma2(hx, wv.x, acc[4][0]); acc[4][0] = fma2(hy, wv.y, acc[4][0]);
                    acc[4][1] = fma2(gx, wv.x, acc[4][1]); acc[4][1] = fma2(gy, wv.y, acc[4][1]);
                    wv = W5[c];
                    acc[5][0] = fma2(hx, wv.x, acc[5][0]); acc[5][0] = fma2(hy, wv.y, acc[5][0]);
                    acc[5][1] = fma2(gx, wv.x, acc[5][1]); acc[5][1] = fma2(gy, wv.y, acc[5][1]);
                }
                // v[combo][g], combo = joff*2 + smp
                float v[4][3];
#pragma unroll
                for (int g = 0; g < 3; ++g) {
                    v[0][g] = red2(acc[g][0]);
                    v[1][g] = red2(acc[g][1]);
                    v[2][g] = red2(acc[3 + g][0]);
                    v[3][g] = red2(acc[3 + g][1]);
                }
                // flush PREVIOUS pair's tail
                if (pjb >= 0) {
                    float fin[3];
#pragma unroll
                    for (int g = 0; g < 3; ++g)
                        fin[g] = px[g] + __shfl_xor_sync(0xffffffffu, px[g], 16);
                    const int j_eff = pjb + o1;
                    float4 g0 = *(const float4*)(gc + j_eff * 8);
                    float4 g1 = *(const float4*)(gc + j_eff * 8 + 4);
                    float rG = sigm(fmaf(d_eff, g1.x, g0.x) + fin[0]);
                    float zG = sigm(fmaf(d_eff, g1.y, g0.y) + fin[1]);
                    float nG = tanh_f(fmaf(d_eff, g1.z, g0.w) + rG * (fin[2] + g0.z));
                    if (wr_h) {
                        const int hidx = s_gru * HP + j_eff;
                        float ho = hbuf[hidx];
                        hbuf[hidx] = (1.f - zG) * nG + zG * ho;
                    }
                }
                // stage1 xor4 (combine sample, route o0) + stage2 xor8 (combine joff, route o1)
                {
                    float zt, tt;
                    float u[2][3];
#pragma unroll
                    for (int c2 = 0; c2 < 2; ++c2)
#pragma unroll
                        for (int g = 0; g < 3; ++g) {
                            zt = o0 ? v[c2 * 2 + 0][g] : v[c2 * 2 + 1][g];
                            tt = __shfl_xor_sync(0xffffffffu, zt, 4);
                            u[c2][g] = (o0 ? v[c2 * 2 + 1][g] : v[c2 * 2 + 0][g]) + tt;
                        }
#pragma unroll
                    for (int g = 0; g < 3; ++g) {
                        zt = o1 ? u[0][g] : u[1][g];
                        tt = __shfl_xor_sync(0xffffffffu, zt, 8);
                        px[g] = (o1 ? u[1][g] : u[0][g]) + tt;
                    }
                }
                pjb = j0 + jp;
            }
            CP_WAIT0();
            __syncthreads();
        }
        // final pending GRU tail
        {
            float fin[3];
#pragma unroll
            for (int g = 0; g < 3; ++g)
                fin[g] = px[g] + __shfl_xor_sync(0xffffffffu, px[g], 16);
            const int j_eff = pjb + o1;
            float4 g0 = *(const float4*)(gc + j_eff * 8);
            float4 g1 = *(const float4*)(gc + j_eff * 8 + 4);
            float rG = sigm(fmaf(d_eff, g1.x, g0.x) + fin[0]);
            float zG = sigm(fmaf(d_eff, g1.y, g0.y) + fin[1]);
            float nG = tanh_f(fmaf(d_eff, g1.z, g0.w) + rG * (fin[2] + g0.z));
            if (wr_h) {
                const int hidx = s_gru * HP + j_eff;
                float ho = hbuf[hidx];
                hbuf[hidx] = (1.f - zG) * nG + zG * ho;
            }
        }
        __syncwarp();   // warp-local h writes visible before re-stash

        // ---- dec L1 [200]->[100] ----
#pragma unroll
        for (int q = 0; q < 2; ++q) {
            const int s = q ? sB : sA;
            float ta[28];
#pragma unroll
            for (int c = 0; c < 25; ++c)
                ta[c] = hbuf[s * HP + 25 * oct + c];
#pragma unroll
            for (int c = 25; c < 28; ++c) ta[c] = 0.f;
#pragma unroll
            for (int c = 0; c < 14; ++c) ha[q][c] = pk(ta[2 * c], ta[2 * c + 1]);
        }
        stage_d1_tile(tb0, 0, 12, tid);
        CP_COMMIT();
        CP_WAIT0();
        __syncthreads();
        float pxx = 0.f;
        int prow = -1;
#pragma unroll 1
        for (int k = 0; k < 9; ++k) {
            float* cur = (k & 1) ? tb1 : tb0;
            float* nxt = (k & 1) ? tb0 : tb1;
            if (k + 1 < 9) {
                int r0n = (k + 1) * 12;
                stage_d1_tile(nxt, r0n, min(12, 100 - r0n), tid);
            }
            CP_COMMIT();
            const int r0 = k * 12;
            const int nr = min(12, 100 - r0);
            const float* cur_o = cur + oct * 28;
#pragma unroll 4
            for (int lr = 0; lr < nr; ++lr) {
                const int row = r0 + lr;
                const ulonglong2* W2 = (const ulonglong2*)(cur_o + lr * TP);
                ull a0 = 0, a1 = 0;
#pragma unroll
                for (int c = 0; c < 7; ++c) {
                    ulonglong2 wv = W2[c];
                    a0 = fma2(ha[0][2 * c], wv.x, a0); a0 = fma2(ha[0][2 * c + 1], wv.y, a0);
                    a1 = fma2(ha[1][2 * c], wv.x, a1); a1 = fma2(ha[1][2 * c + 1], wv.y, a1);
                }
                float v0 = red2(a0), v1 = red2(a1);
                if (prow >= 0) {
                    float fv = pxx + __shfl_xor_sync(0xffffffffu, pxx, 16);
                    if (wr_y1)
                        smY1[s_dl1 * Y1P + prow] = lrelu(fv + cb1[prow]);
                }
                float zt = o0 ? v0 : v1;
                float tt = __shfl_xor_sync(0xffffffffu, zt, 4);
                float uu = (o0 ? v1 : v0) + tt;
                uu += __shfl_xor_sync(0xffffffffu, uu, 8);
                pxx = uu;
                prow = row;
            }
            CP_WAIT0();
            __syncthreads();
        }
        {
            float fv = pxx + __shfl_xor_sync(0xffffffffu, pxx, 16);
            if (wr_y1)
                smY1[s_dl1 * Y1P + prow] = lrelu(fv + cb1[prow]);
        }
        __syncwarp();

        // ---- dec L2 [100]->[50] ----
        const int q2 = lane >> 3;
        const int s2 = lane & 7;
        const int samp = w * 8 + s2;
        ull ya[14];
        {
            float tv[28];
#pragma unroll
            for (int c = 0; c < 25; ++c) tv[c] = smY1[samp * Y1P + 25 * q2 + c];
#pragma unroll
            for (int c = 25; c < 28; ++c) tv[c] = 0.f;
#pragma unroll
            for (int c = 0; c < 14; ++c) ya[c] = pk(tv[2 * c], tv[2 * c + 1]);
        }
        stage_d2_tile(tb0, 0, 12, tid);
        CP_COMMIT();
        CP_WAIT0();
        __syncthreads();   // y1 reads done before y2 overlay writes
        float* smY2 = smY1;
        const bool wr_y2 = (q2 == 0);
        float pu = 0.f;
        int prow2 = -1;
#pragma unroll 1
        for (int k = 0; k < 5; ++k) {
            float* cur = (k & 1) ? tb1 : tb0;
            float* nxt = (k & 1) ? tb0 : tb1;
            if (k + 1 < 5) {
                int r0n = (k + 1) * 12;
                stage_d2_tile(nxt, r0n, min(12, 50 - r0n), tid);
            }
            CP_COMMIT();
            const int r0 = k * 12;
            const int nr = min(12, 50 - r0);
            const float* cur_q = cur + q2 * 28;
#pragma unroll 4
            for (int lr = 0; lr < nr; ++lr) {
                const int row = r0 + lr;
                const ulonglong2* W2 = (const ulonglong2*)(cur_q + lr * TP2);
                ull a0 = 0;
#pragma unroll
                for (int c = 0; c < 7; ++c) {
                    ulonglong2 wv = W2[c];
                    a0 = fma2(ya[2 * c], wv.x, a0);
                    a0 = fma2(ya[2 * c + 1], wv.y, a0);
                }
                float v0 = red2(a0);
                if (prow2 >= 0) {
                    float fu = pu + __shfl_xor_sync(0xffffffffu, pu, 16);
                    if (wr_y2)
                        smY2[samp * Y2P + prow2] = lrelu(fu + cb2[prow2]);
                }
                pu = v0 + __shfl_xor_sync(0xffffffffu, v0, 8);
                prow2 = row;
            }
            CP_WAIT0();
            __syncthreads();
        }
        {
            float fu = pu + __shfl_xor_sync(0xffffffffu, pu, 16);
            if (wr_y2)
                smY2[samp * Y2P + prow2] = lrelu(fu + cb2[prow2]);
        }
        __syncthreads();

        // ---- dec L3 + feedback ----
        if (tid < BT) {
            float acc = b3s[0];
            for (int c = 0; c < 50; ++c)
                acc += smY2[tid * Y2P + c] * w3s[c];
            out[((size_t)(cta * BT + tid)) * LD + t] = acc;
            din[tid] = acc;
        }
        __syncthreads();
    }
}

extern "C" void kernel_launch(void* const* d_in, const int* in_sizes, int n_in,
                              void* d_out, int out_size) {
    const float* enc_in = (const float*)d_in[0];
    const float* enc_w1 = (const float*)d_in[1];
    const float* enc_b1 = (const float*)d_in[2];
    const float* enc_w2 = (const float*)d_in[3];
    const float* enc_b2 = (const float*)d_in[4];
    const float* enc_wl = (const float*)d_in[5];
    const float* enc_bl = (const float*)d_in[6];
    const float* w_ih   = (const float*)d_in[7];
    const float* w_hh   = (const float*)d_in[8];
    const float* b_ih   = (const float*)d_in[9];
    const float* b_hh   = (const float*)d_in[10];
    const float* dec_w1 = (const float*)d_in[11];
    const float* dec_b1 = (const float*)d_in[12];
    const float* dec_w2 = (const float*)d_in[13];
    const float* dec_b2 = (const float*)d_in[14];
    const float* dec_w3 = (const float*)d_in[15];
    const float* dec_b3 = (const float*)d_in[16];
    float* out = (float*)d_out;

    const int prep_total = 25 * 24 * 224 + 100 * 224 + 50 * 112;
    prep_kernel<<<(prep_total + 255) / 256, 256>>>(w_hh, dec_w1, dec_w2);

    cudaFuncSetAttribute(seq2seq_gru_kernel,
                         cudaFuncAttributeMaxDynamicSharedMemorySize, SMEM_BYTES);
    seq2seq_gru_kernel<<<NS / BT, THREADS, SMEM_BYTES>>>(
        enc_in, enc_w1, enc_b1, enc_w2, enc_b2, enc_wl, enc_bl,
        w_ih, w_hh, b_ih, b_hh,
        dec_b1, dec_b2, dec_w3, dec_b3, out);
}

// round 16
// speedup vs baseline: 1.1764x; 1.1764x over previous
#include <cuda_runtime.h>
#include <math.h>

#define NS 131072
#define LE 100
#define LD 50
#define HD 200
#define SPD 202
#define BT 64
#define THREADS 128
#define HP 204
#define Y1P 104
#define Y2P 52
#define TP 224
#define TP2 112

typedef unsigned long long ull;

__device__ float gruT[25 * 24 * 224];
__device__ float d1T[100 * 224];
__device__ float d2T[50 * 112];

__device__ __forceinline__ ull fma2(ull a, ull b, ull c) {
    ull d;
    asm("fma.rn.f32x2 %0, %1, %2, %3;" : "=l"(d) : "l"(a), "l"(b), "l"(c));
    return d;
}
__device__ __forceinline__ float red2(ull v) {
    float lo, hi;
    asm("mov.b64 {%0, %1}, %2;" : "=f"(lo), "=f"(hi) : "l"(v));
    return lo + hi;
}
__device__ __forceinline__ ull pk(float lo, float hi) {
    ull r;
    asm("mov.b64 %0, {%1, %2};" : "=l"(r) : "f"(lo), "f"(hi));
    return r;
}
__device__ __forceinline__ unsigned su32(const void* p) {
    return (unsigned)__cvta_generic_to_shared(p);
}
__device__ __forceinline__ void cpa16(unsigned dst, const void* src) {
    asm volatile("cp.async.cg.shared.global [%0], [%1], 16;" :: "r"(dst), "l"(src));
}
#define CP_COMMIT() asm volatile("cp.async.commit_group;" ::: "memory")
#define CP_WAIT0()  asm volatile("cp.async.wait_group 0;" ::: "memory")

template <int N2>
__device__ __forceinline__ float dotAB(const float* __restrict__ a, const float* __restrict__ b) {
    const ulonglong2* A2 = (const ulonglong2*)a;
    const ull* B = (const ull*)b;
    ull a0 = 0ull, a1 = 0ull;
#pragma unroll
    for (int i = 0; i < N2 / 2; ++i) {
        ulonglong2 x = A2[i];
        a0 = fma2(x.x, B[2 * i], a0);
        a1 = fma2(x.y, B[2 * i + 1], a1);
    }
    if (N2 & 1) a0 = fma2(((const ull*)a)[N2 - 1], B[N2 - 1], a0);
    return red2(a0) + red2(a1);
}

__device__ __forceinline__ float lrelu(float x) { return x > 0.f ? x : 0.01f * x; }
__device__ __forceinline__ float sigm(float x) {
    return __fdividef(1.0f, 1.0f + __expf(-x));
}
__device__ __forceinline__ float tanh_f(float x) {
    float t = __expf(-2.0f * fabsf(x));
    float r = __fdividef(1.0f - t, 1.0f + t);
    return copysignf(r, x);
}

// smem map (floats)
#define OFF_H    0
#define OFF_Y1   13056
#define OFF_TA   19712
#define OFF_T0   19712
#define OFF_T1   22400
#define OFF_GC   25088
#define OFF_B1   26688
#define OFF_B2   26788
#define OFF_W3   26838
#define OFF_B3   26888
#define OFF_DIN  26892
#define OFF_CT   26956
#define OFF_ST   27056
#define SMEM_FLOATS 27156
#define SMEM_BYTES  (SMEM_FLOATS * 4)

__global__ void prep_kernel(const float* __restrict__ w_hh,
                            const float* __restrict__ dec_w1,
                            const float* __restrict__ dec_w2) {
    int idx = blockIdx.x * blockDim.x + threadIdx.x;
    if (idx < 25 * 24 * 224) {
        int k = idx / (24 * 224);
        int rem = idx - k * (24 * 224);
        int row = rem / 224, col = rem - row * 224;
        int jj = row / 3, g = row - jj * 3;
        int oct = col / 28, c = col - oct * 28;
        float v = 0.f;
        if (c < 25) v = w_hh[(size_t)(g * 200 + k * 8 + jj) * 200 + 25 * oct + c];
        gruT[idx] = v;
        return;
    }
    int idx2 = idx - 25 * 24 * 224;
    if (idx2 < 100 * 224) {
        int row = idx2 / 224, col = idx2 - row * 224;
        int oct = col / 28, c = col - oct * 28;
        d1T[idx2] = (c < 25) ? dec_w1[(size_t)row * 200 + 25 * oct + c] : 0.f;
        return;
    }
    int idx3 = idx2 - 100 * 224;
    if (idx3 < 50 * 112) {
        int row = idx3 / 112, col = idx3 - row * 112;
        int q = col / 28, c = col - q * 28;
        d2T[idx3] = (c < 25) ? dec_w2[(size_t)row * 100 + 25 * q + c] : 0.f;
    }
}

__device__ __forceinline__ void stage_gru_tile(float* buf, int k, int tid) {
    const float4* src = (const float4*)(gruT + k * (24 * 224));
    unsigned d = su32(buf);
#pragma unroll
    for (int rep = 0; rep < 11; ++rep) {
        int i = tid + rep * THREADS;
        if (i < 1344) cpa16(d + i * 16, src + i);
    }
}
__device__ __forceinline__ void stage_d1_tile(float* buf, int r0, int nrows, int tid) {
    const float4* src = (const float4*)(d1T + r0 * 224);
    unsigned d = su32(buf);
    int n = nrows * 56;
#pragma unroll
    for (int rep = 0; rep < 6; ++rep) {
        int i = tid + rep * THREADS;
        if (i < n) cpa16(d + i * 16, src + i);
    }
}
__device__ __forceinline__ void stage_d2_tile(float* buf, int r0, int nrows, int tid) {
    const float4* src = (const float4*)(d2T + r0 * 112);
    unsigned d = su32(buf);
    int n = nrows * 28;
#pragma unroll
    for (int rep = 0; rep < 3; ++rep) {
        int i = tid + rep * THREADS;
        if (i < n) cpa16(d + i * 16, src + i);
    }
}

__global__ void __launch_bounds__(THREADS, 2)
seq2seq_gru_kernel(
    const float* __restrict__ enc_in,
    const float* __restrict__ enc_w1, const float* __restrict__ enc_b1,
    const float* __restrict__ enc_w2, const float* __restrict__ enc_b2,
    const float* __restrict__ enc_wl, const float* __restrict__ enc_bl,
    const float* __restrict__ w_ih,  const float* __restrict__ w_hh,
    const float* __restrict__ b_ih,  const float* __restrict__ b_hh,
    const float* __restrict__ dec_b1, const float* __restrict__ dec_b2,
    const float* __restrict__ dec_w3, const float* __restrict__ dec_b3,
    float* __restrict__ out)
{
    extern __shared__ float sm[];
    float* hbuf = sm + OFF_H;
    float* smY1 = sm + OFF_Y1;
    float* tbA  = sm + OFF_TA;
    float* tb0  = sm + OFF_T0;
    float* tb1  = sm + OFF_T1;
    float* gc   = sm + OFF_GC;
    float* cb1  = sm + OFF_B1;
    float* cb2  = sm + OFF_B2;
    float* w3s  = sm + OFF_W3;
    float* b3s  = sm + OFF_B3;
    float* din  = sm + OFF_DIN;
    float* ctab = sm + OFF_CT;
    float* stab = sm + OFF_ST;

    const int tid  = threadIdx.x;
    const int lane = tid & 31;
    const int w    = tid >> 5;          // 4 warps
    const int cta  = blockIdx.x;
    const float* inbase = enc_in + (size_t)cta * BT * LE;
    float* sig = hbuf;

    for (int idx = tid; idx < BT * LE; idx += THREADS) {
        int s = idx / LE, t = idx - s * LE;
        sig[s * HP + t] = inbase[idx];
    }
    if (tid < 100) {
        float u = (float)tid / 50.0f;
        ctab[tid] = cospif(u);
        stab[tid] = sinpif(u);
    }
    if (tid < BT) din[tid] = inbase[tid * LE + (LE - 1)];
    for (int j = tid; j < 200; j += THREADS) {
        gc[j * 8 + 0] = b_ih[j] + b_hh[j];
        gc[j * 8 + 1] = b_ih[HD + j] + b_hh[HD + j];
        gc[j * 8 + 2] = b_hh[2 * HD + j];
        gc[j * 8 + 3] = b_ih[2 * HD + j];
        gc[j * 8 + 4] = w_ih[j];
        gc[j * 8 + 5] = w_ih[HD + j];
        gc[j * 8 + 6] = w_ih[2 * HD + j];
        gc[j * 8 + 7] = 0.f;
    }
    if (tid < 100) cb1[tid] = dec_b1[tid];
    if (tid < 50)  { cb2[tid] = dec_b2[tid]; w3s[tid] = dec_w3[tid]; }
    if (tid == 0)  b3s[0] = dec_b3[0];
    __syncthreads();

    // DFT features
    for (int kk = 0; kk < 13; ++kk) {
        int k = w + 4 * kk;
        if (k < 51) {
#pragma unroll
            for (int p = 0; p < 2; ++p) {
                int s = lane + 32 * p;
                const float* xr = sig + s * HP;
                float re = 0.f, im = 0.f;
                int m = 0;
                for (int t = 0; t < LE; ++t) {
                    float xv = xr[t];
                    re += xv * ctab[m];
                    im -= xv * stab[m];
                    m += k; if (m >= 100) m -= 100;
                }
                re *= 0.01f; im *= 0.01f;
                if (k == 0 || k == 50) im = 0.0f;
                sig[s * HP + 100 + k] = sqrtf(re * re + im * im);
                sig[s * HP + 151 + k] = atan2f(im, re);
            }
        }
    }
    __syncthreads();

    // encoder L1 [202]->[100]
    {
        float* xbuf = smY1;
        for (int ii = 0; ii < 25; ++ii) {
            int i = w + 4 * ii;
            float b = enc_b1[i];
            const float* wr = enc_w1 + (size_t)i * SPD;
#pragma unroll
            for (int p = 0; p < 2; ++p) {
                int s = lane + 32 * p;
                xbuf[s * 100 + i] = lrelu(dotAB<101>(sig + s * HP, wr) + b);
            }
        }
        __syncthreads();
        // encoder L2 [100]->[202]
        for (int ii = 0; ii < 51; ++ii) {
            int i = w + 4 * ii;
            if (i < SPD) {
                float b = enc_b2[i];
                const float* wr = enc_w2 + (size_t)i * 100;
#pragma unroll
                for (int p = 0; p < 2; ++p) {
                    int s = lane + 32 * p;
                    sig[s * HP + i] = lrelu(dotAB<50>(xbuf + s * 100, wr) + b);
                }
            }
        }
        __syncthreads();
    }
    // encoder final [202]->[200] -> h0 in-place via tmp
    for (int half = 0; half < 2; ++half) {
        float* tmp = smY1;
        for (int ii = 0; ii < 50; ++ii) {
            int i = w + 4 * ii;
            int s = lane + 32 * half;
            tmp[lane * 200 + i] = dotAB<101>(sig + s * HP, enc_wl + (size_t)i * SPD) + enc_bl[i];
        }
        __syncthreads();
        for (int idx = tid; idx < 32 * 200; idx += THREADS) {
            int sp_ = idx / 200, i = idx - sp_ * 200;
            hbuf[(32 * half + sp_) * HP + i] = tmp[idx];
        }
        __syncthreads();
    }

    const int oct = lane >> 2;           // K-eighth
    const int sp  = lane & 3;
    const int sbase = w * 16 + sp * 4;   // lane owns samples sbase..sbase+3
    const int o0 = oct & 1, o1 = (oct >> 1) & 1, o2 = oct >> 2;
    const int q_lane = oct >> 1;
    const int s_gru = sbase + q_lane;
    const int s_dl1 = sbase + (oct & 3);
    const bool wr_y1 = (o2 == 0);

    // prefetch GRU tile 0 for step 0 (tbA is free after encoder)
    stage_gru_tile(tbA, 0, tid);
    CP_COMMIT();

    for (int t = 0; t < LD; ++t) {
        ull ha[4][14];
#pragma unroll
        for (int q = 0; q < 4; ++q) {
            float ta[28];
#pragma unroll
            for (int c = 0; c < 25; ++c)
                ta[c] = hbuf[(sbase + q) * HP + 25 * oct + c];
#pragma unroll
            for (int c = 25; c < 28; ++c) ta[c] = 0.f;
#pragma unroll
            for (int c = 0; c < 14; ++c) ha[q][c] = pk(ta[2 * c], ta[2 * c + 1]);
        }
        const float d_eff = din[s_gru];

        // ---- GRU: 25 tiles of 8 j (tile 0 prefetched last step) ----
        CP_WAIT0();
        __syncthreads();
        float px[2][3];
        int pjb = -1;
#pragma unroll 1
        for (int k = 0; k < 25; ++k) {
            float* cur = (k & 1) ? smY1 : tbA;
            float* nxt = (k & 1) ? tbA : smY1;
            if (k + 1 < 25) { stage_gru_tile(nxt, k + 1, tid); }
            CP_COMMIT();
            const int j0 = k * 8;
            const float* cur_o = cur + oct * 28;
#pragma unroll 1
            for (int jp = 0; jp < 8; jp += 2) {
                const float* rowp = cur_o + jp * 3 * TP;
                const ulonglong2* W0 = (const ulonglong2*)(rowp + 0 * TP);
                const ulonglong2* W1 = (const ulonglong2*)(rowp + 1 * TP);
                const ulonglong2* W2 = (const ulonglong2*)(rowp + 2 * TP);
                const ulonglong2* W3 = (const ulonglong2*)(rowp + 3 * TP);
                const ulonglong2* W4 = (const ulonglong2*)(rowp + 4 * TP);
                const ulonglong2* W5 = (const ulonglong2*)(rowp + 5 * TP);
                ull acc[6][4];
#pragma unroll
                for (int r = 0; r < 6; ++r)
#pragma unroll
                    for (int q = 0; q < 4; ++q) acc[r][q] = 0ull;
#pragma unroll
                for (int c = 0; c < 7; ++c) {
                    ulonglong2 wv0 = W0[c], wv1 = W1[c], wv2 = W2[c];
                    ulonglong2 wv3 = W3[c], wv4 = W4[c], wv5 = W5[c];
#pragma unroll
                    for (int q = 0; q < 4; ++q) {
                        ull hx = ha[q][2 * c], hy = ha[q][2 * c + 1];
                        acc[0][q] = fma2(hx, wv0.x, acc[0][q]); acc[0][q] = fma2(hy, wv0.y, acc[0][q]);
                        acc[1][q] = fma2(hx, wv1.x, acc[1][q]); acc[1][q] = fma2(hy, wv1.y, acc[1][q]);
                        acc[2][q] = fma2(hx, wv2.x, acc[2][q]); acc[2][q] = fma2(hy, wv2.y, acc[2][q]);
                        acc[3][q] = fma2(hx, wv3.x, acc[3][q]); acc[3][q] = fma2(hy, wv3.y, acc[3][q]);
                        acc[4][q] = fma2(hx, wv4.x, acc[4][q]); acc[4][q] = fma2(hy, wv4.y, acc[4][q]);
                        acc[5][q] = fma2(hx, wv5.x, acc[5][q]); acc[5][q] = fma2(hy, wv5.y, acc[5][q]);
                    }
                }
                float v[8][3];
#pragma unroll
                for (int q = 0; q < 4; ++q)
#pragma unroll
                    for (int g = 0; g < 3; ++g) {
                        v[q * 2 + 0][g] = red2(acc[g][q]);
                        v[q * 2 + 1][g] = red2(acc[3 + g][q]);
                    }
                // flush PREVIOUS pair-round's tail
                if (pjb >= 0) {
                    float fin[3], zt, tt;
#pragma unroll
                    for (int g = 0; g < 3; ++g) {
                        zt = o2 ? px[0][g] : px[1][g];
                        tt = __shfl_xor_sync(0xffffffffu, zt, 16);
                        fin[g] = (o2 ? px[1][g] : px[0][g]) + tt;
                    }
                    const int j_eff = pjb + o0;
                    float4 g0 = *(const float4*)(gc + j_eff * 8);
                    float4 g1 = *(const float4*)(gc + j_eff * 8 + 4);
                    float rG = sigm(fmaf(d_eff, g1.x, g0.x) + fin[0]);
                    float zG = sigm(fmaf(d_eff, g1.y, g0.y) + fin[1]);
                    float nG = tanh_f(fmaf(d_eff, g1.z, g0.w) + rG * (fin[2] + g0.z));
                    const int hidx = s_gru * HP + j_eff;
                    float ho = hbuf[hidx];
                    hbuf[hidx] = (1.f - zG) * nG + zG * ho;
                }
                // stage1 xor4 + stage2 xor8 for CURRENT round
                {
                    float zt, tt;
                    float u[4][3];
#pragma unroll
                    for (int q = 0; q < 4; ++q)
#pragma unroll
                        for (int g = 0; g < 3; ++g) {
                            zt = o0 ? v[q * 2 + 0][g] : v[q * 2 + 1][g];
                            tt = __shfl_xor_sync(0xffffffffu, zt, 4);
                            u[q][g] = (o0 ? v[q * 2 + 1][g] : v[q * 2 + 0][g]) + tt;
                        }
#pragma unroll
                    for (int qh = 0; qh < 2; ++qh)
#pragma unroll
                        for (int g = 0; g < 3; ++g) {
                            zt = o1 ? u[qh * 2 + 0][g] : u[qh * 2 + 1][g];
                            tt = __shfl_xor_sync(0xffffffffu, zt, 8);
                            px[qh][g] = (o1 ? u[qh * 2 + 1][g] : u[qh * 2 + 0][g]) + tt;
                        }
                }
                pjb = j0 + jp;
            }
            CP_WAIT0();
            __syncthreads();
        }
        // prefetch dec L1 tile 0 (tbA free now); hidden behind tail + restash
        stage_d1_tile(tb0, 0, 12, tid);
        CP_COMMIT();
        // final pending GRU tail
        {
            float fin[3], zt, tt;
#pragma unroll
            for (int g = 0; g < 3; ++g) {
                zt = o2 ? px[0][g] : px[1][g];
                tt = __shfl_xor_sync(0xffffffffu, zt, 16);
                fin[g] = (o2 ? px[1][g] : px[0][g]) + tt;
            }
            const int j_eff = pjb + o0;
            float4 g0 = *(const float4*)(gc + j_eff * 8);
            float4 g1 = *(const float4*)(gc + j_eff * 8 + 4);
            float rG = sigm(fmaf(d_eff, g1.x, g0.x) + fin[0]);
            float zG = sigm(fmaf(d_eff, g1.y, g0.y) + fin[1]);
            float nG = tanh_f(fmaf(d_eff, g1.z, g0.w) + rG * (fin[2] + g0.z));
            const int hidx = s_gru * HP + j_eff;
            float ho = hbuf[hidx];
            hbuf[hidx] = (1.f - zG) * nG + zG * ho;
        }
        __syncwarp();

        // ---- dec L1 [200]->[100] ----
#pragma unroll
        for (int q = 0; q < 4; ++q) {
            float ta[28];
#pragma unroll
            for (int c = 0; c < 25; ++c)
                ta[c] = hbuf[(sbase + q) * HP + 25 * oct + c];
#pragma unroll
            for (int c = 25; c < 28; ++c) ta[c] = 0.f;
#pragma unroll
            for (int c = 0; c < 14; ++c) ha[q][c] = pk(ta[2 * c], ta[2 * c + 1]);
        }
        CP_WAIT0();
        __syncthreads();
        float pxx = 0.f;
        int prow = -1;
#pragma unroll 1
        for (int k = 0; k < 9; ++k) {
            float* cur = (k & 1) ? tb1 : tb0;
            float* nxt = (k & 1) ? tb0 : tb1;
            if (k + 1 < 9) {
                int r0n = (k + 1) * 12;
                stage_d1_tile(nxt, r0n, min(12, 100 - r0n), tid);
            } else {
                // prefetch dec L2 tile 0 into the free buffer (tb1 at k=8)
                stage_d2_tile(nxt, 0, 12, tid);
            }
            CP_COMMIT();
            const int r0 = k * 12;
            const int nr = min(12, 100 - r0);
            const float* cur_o = cur + oct * 28;
#pragma unroll 4
            for (int lr = 0; lr < nr; ++lr) {
                const int row = r0 + lr;
                const ulonglong2* W2 = (const ulonglong2*)(cur_o + lr * TP);
                ull a0 = 0, a1 = 0, a2 = 0, a3 = 0;
#pragma unroll
                for (int c = 0; c < 7; ++c) {
                    ulonglong2 wv = W2[c];
                    a0 = fma2(ha[0][2 * c], wv.x, a0); a0 = fma2(ha[0][2 * c + 1], wv.y, a0);
                    a1 = fma2(ha[1][2 * c], wv.x, a1); a1 = fma2(ha[1][2 * c + 1], wv.y, a1);
                    a2 = fma2(ha[2][2 * c], wv.x, a2); a2 = fma2(ha[2][2 * c + 1], wv.y, a2);
                    a3 = fma2(ha[3][2 * c], wv.x, a3); a3 = fma2(ha[3][2 * c + 1], wv.y, a3);
                }
                float v0 = red2(a0), v1 = red2(a1), v2 = red2(a2), v3 = red2(a3);
                if (prow >= 0) {
                    float fv = pxx + __shfl_xor_sync(0xffffffffu, pxx, 16);
                    if (wr_y1)
                        smY1[s_dl1 * Y1P + prow] = lrelu(fv + cb1[prow]);
                }
                float zt, tt, u0, u1;
                zt = o0 ? v0 : v1;
                tt = __shfl_xor_sync(0xffffffffu, zt, 4);
                u0 = (o0 ? v1 : v0) + tt;
                zt = o0 ? v2 : v3;
                tt = __shfl_xor_sync(0xffffffffu, zt, 4);
                u1 = (o0 ? v3 : v2) + tt;
                zt = o1 ? u0 : u1;
                tt = __shfl_xor_sync(0xffffffffu, zt, 8);
                pxx = (o1 ? u1 : u0) + tt;
                prow = row;
            }
            CP_WAIT0();
            __syncthreads();
        }
        {
            float fv = pxx + __shfl_xor_sync(0xffffffffu, pxx, 16);
            if (wr_y1)
                smY1[s_dl1 * Y1P + prow] = lrelu(fv + cb1[prow]);
        }
        __syncwarp();

        // ---- dec L2 [100]->[50]; tile 0 already in tb1 ----
        const int q2 = lane >> 3;
        const int s2 = lane & 7;
        const int sampA = w * 16 + s2;
        const int sampB = sampA + 8;
        ull ya[2][14];
#pragma unroll
        for (int v = 0; v < 2; ++v) {
            int samp = v ? sampB : sampA;
            float tv[28];
#pragma unroll
            for (int c = 0; c < 25; ++c) tv[c] = smY1[samp * Y1P + 25 * q2 + c];
#pragma unroll
            for (int c = 25; c < 28; ++c) tv[c] = 0.f;
#pragma unroll
            for (int c = 0; c < 14; ++c) ya[v][c] = pk(tv[2 * c], tv[2 * c + 1]);
        }
        CP_WAIT0();
        __syncthreads();   // y1 stashes done before y2 overlay writes
        float* smY2 = smY1;
        const int q2b0 = q2 & 1;
        const int s_dl2 = q2b0 ? sampB : sampA;
        const bool wr_y2 = (q2 < 2);
        float pu = 0.f;
        int prow2 = -1;
#pragma unroll 1
        for (int k = 0; k < 5; ++k) {
            float* cur = (k & 1) ? tb0 : tb1;   // parity flipped: tile0 in tb1
            float* nxt = (k & 1) ? tb1 : tb0;
            if (k + 1 < 5) {
                int r0n = (k + 1) * 12;
                stage_d2_tile(nxt, r0n, min(12, 50 - r0n), tid);
            }
            CP_COMMIT();
            const int r0 = k * 12;
            const int nr = min(12, 50 - r0);
            const float* cur_q = cur + q2 * 28;
#pragma unroll 4
            for (int lr = 0; lr < nr; ++lr) {
                const int row = r0 + lr;
                const ulonglong2* W2 = (const ulonglong2*)(cur_q + lr * TP2);
                ull a0 = 0, a1 = 0;
#pragma unroll
                for (int c = 0; c < 7; ++c) {
                    ulonglong2 wv = W2[c];
                    a0 = fma2(ya[0][2 * c], wv.x, a0); a0 = fma2(ya[0][2 * c + 1], wv.y, a0);
                    a1 = fma2(ya[1][2 * c], wv.x, a1); a1 = fma2(ya[1][2 * c + 1], wv.y, a1);
                }
                float v0 = red2(a0), v1 = red2(a1);
                if (prow2 >= 0) {
                    float fu = pu + __shfl_xor_sync(0xffffffffu, pu, 16);
                    if (wr_y2)
                        smY2[s_dl2 * Y2P + prow2] = lrelu(fu + cb2[prow2]);
                }
                float zt = q2b0 ? v0 : v1;
                float tt = __shfl_xor_sync(0xffffffffu, zt, 8);
                pu = (q2b0 ? v1 : v0) + tt;
                prow2 = row;
            }
            CP_WAIT0();
            __syncthreads();
        }
        {
            float fu = pu + __shfl_xor_sync(0xffffffffu, pu, 16);
            if (wr_y2)
                smY2[s_dl2 * Y2P + prow2] = lrelu(fu + cb2[prow2]);
        }
        // prefetch next step's GRU tile 0 (tbA free); hidden behind dec L3
        if (t + 1 < LD) {
            stage_gru_tile(tbA, 0, tid);
            CP_COMMIT();
        }
        __syncthreads();

        // ---- dec L3 + feedback ----
        if (tid < BT) {
            float acc = b3s[0];
            for (int c = 0; c < 50; ++c)
                acc += smY2[tid * Y2P + c] * w3s[c];
            out[((size_t)(cta * BT + tid)) * LD + t] = acc;
            din[tid] = acc;
        }
        __syncthreads();
    }
}

extern "C" void kernel_launch(void* const* d_in, const int* in_sizes, int n_in,
                              void* d_out, int out_size) {
    const float* enc_in = (const float*)d_in[0];
    const float* enc_w1 = (const float*)d_in[1];
    const float* enc_b1 = (const float*)d_in[2];
    const float* enc_w2 = (const float*)d_in[3];
    const float* enc_b2 = (const float*)d_in[4];
    const float* enc_wl = (const float*)d_in[5];
    const float* enc_bl = (const float*)d_in[6];
    const float* w_ih   = (const float*)d_in[7];
    const float* w_hh   = (const float*)d_in[8];
    const float* b_ih   = (const float*)d_in[9];
    const float* b_hh   = (const float*)d_in[10];
    const float* dec_w1 = (const float*)d_in[11];
    const float* dec_b1 = (const float*)d_in[12];
    const float* dec_w2 = (const float*)d_in[13];
    const float* dec_b2 = (const float*)d_in[14];
    const float* dec_w3 = (const float*)d_in[15];
    const float* dec_b3 = (const float*)d_in[16];
    float* out = (float*)d_out;

    const int prep_total = 25 * 24 * 224 + 100 * 224 + 50 * 112;
    prep_kernel<<<(prep_total + 255) / 256, 256>>>(w_hh, dec_w1, dec_w2);

    cudaFuncSetAttribute(seq2seq_gru_kernel,
                         cudaFuncAttributeMaxDynamicSharedMemorySize, SMEM_BYTES);
    seq2seq_gru_kernel<<<NS / BT, THREADS, SMEM_BYTES>>>(
        enc_in, enc_w1, enc_b1, enc_w2, enc_b2, enc_wl, enc_bl,
        w_ih, w_hh, b_ih, b_hh,
        dec_b1, dec_b2, dec_w3, dec_b3, out);
}

// round 17
// speedup vs baseline: 1.1845x; 1.0069x over previous
#include <cuda_runtime.h>
#include <math.h>

#define NS 131072
#define LE 100
#define LD 50
#define HD 200
#define SPD 202
#define BT 64
#define THREADS 128
#define HP 204
#define Y1P 104
#define Y2P 52
#define TP 224
#define TP2 112

typedef unsigned long long ull;

__device__ float gruT[25 * 24 * 224];
__device__ float d1T[100 * 224];
__device__ float d2T[50 * 112];

__device__ __forceinline__ ull fma2(ull a, ull b, ull c) {
    ull d;
    asm("fma.rn.f32x2 %0, %1, %2, %3;" : "=l"(d) : "l"(a), "l"(b), "l"(c));
    return d;
}
__device__ __forceinline__ float red2(ull v) {
    float lo, hi;
    asm("mov.b64 {%0, %1}, %2;" : "=f"(lo), "=f"(hi) : "l"(v));
    return lo + hi;
}
__device__ __forceinline__ ull pk(float lo, float hi) {
    ull r;
    asm("mov.b64 %0, {%1, %2};" : "=l"(r) : "f"(lo), "f"(hi));
    return r;
}
__device__ __forceinline__ unsigned su32(const void* p) {
    return (unsigned)__cvta_generic_to_shared(p);
}
__device__ __forceinline__ void cpa16(unsigned dst, const void* src) {
    asm volatile("cp.async.cg.shared.global [%0], [%1], 16;" :: "r"(dst), "l"(src));
}
#define CP_COMMIT() asm volatile("cp.async.commit_group;" ::: "memory")
#define CP_WAIT0()  asm volatile("cp.async.wait_group 0;" ::: "memory")

template <int N2>
__device__ __forceinline__ float dotAB(const float* __restrict__ a, const float* __restrict__ b) {
    const ulonglong2* A2 = (const ulonglong2*)a;
    const ull* B = (const ull*)b;
    ull a0 = 0ull, a1 = 0ull;
#pragma unroll
    for (int i = 0; i < N2 / 2; ++i) {
        ulonglong2 x = A2[i];
        a0 = fma2(x.x, B[2 * i], a0);
        a1 = fma2(x.y, B[2 * i + 1], a1);
    }
    if (N2 & 1) a0 = fma2(((const ull*)a)[N2 - 1], B[N2 - 1], a0);
    return red2(a0) + red2(a1);
}

__device__ __forceinline__ float lrelu(float x) { return x > 0.f ? x : 0.01f * x; }
__device__ __forceinline__ float sigm(float x) {
    return __fdividef(1.0f, 1.0f + __expf(-x));
}
__device__ __forceinline__ float tanh_f(float x) {
    float t = __expf(-2.0f * fabsf(x));
    float r = __fdividef(1.0f - t, 1.0f + t);
    return copysignf(r, x);
}

// smem map (floats)
#define OFF_H    0
#define OFF_Y1   13056
#define OFF_TA   19712
#define OFF_T0   19712
#define OFF_T1   22400
#define OFF_GC   25088
#define OFF_B1   26688
#define OFF_B2   26788
#define OFF_W3   26838
#define OFF_B3   26888
#define OFF_DIN  26892
#define OFF_CT   26956
#define OFF_ST   27056
#define SMEM_FLOATS 27156
#define SMEM_BYTES  (SMEM_FLOATS * 4)

__global__ void prep_kernel(const float* __restrict__ w_hh,
                            const float* __restrict__ dec_w1,
                            const float* __restrict__ dec_w2) {
    int idx = blockIdx.x * blockDim.x + threadIdx.x;
    if (idx < 25 * 24 * 224) {
        int k = idx / (24 * 224);
        int rem = idx - k * (24 * 224);
        int row = rem / 224, col = rem - row * 224;
        int jj = row / 3, g = row - jj * 3;
        int oct = col / 28, c = col - oct * 28;
        float v = 0.f;
        if (c < 25) v = w_hh[(size_t)(g * 200 + k * 8 + jj) * 200 + 25 * oct + c];
        gruT[idx] = v;
        return;
    }
    int idx2 = idx - 25 * 24 * 224;
    if (idx2 < 100 * 224) {
        int row = idx2 / 224, col = idx2 - row * 224;
        int oct = col / 28, c = col - oct * 28;
        d1T[idx2] = (c < 25) ? dec_w1[(size_t)row * 200 + 25 * oct + c] : 0.f;
        return;
    }
    int idx3 = idx2 - 100 * 224;
    if (idx3 < 50 * 112) {
        int row = idx3 / 112, col = idx3 - row * 112;
        int q = col / 28, c = col - q * 28;
        d2T[idx3] = (c < 25) ? dec_w2[(size_t)row * 100 + 25 * q + c] : 0.f;
    }
}

__device__ __forceinline__ void stage_gru_tile(float* buf, int k, int tid) {
    const float4* src = (const float4*)(gruT + k * (24 * 224));
    unsigned d = su32(buf);
#pragma unroll
    for (int rep = 0; rep < 11; ++rep) {
        int i = tid + rep * THREADS;
        if (i < 1344) cpa16(d + i * 16, src + i);
    }
}
__device__ __forceinline__ void stage_d1_tile(float* buf, int r0, int nrows, int tid) {
    const float4* src = (const float4*)(d1T + r0 * 224);
    unsigned d = su32(buf);
    int n = nrows * 56;
#pragma unroll
    for (int rep = 0; rep < 6; ++rep) {
        int i = tid + rep * THREADS;
        if (i < n) cpa16(d + i * 16, src + i);
    }
}
__device__ __forceinline__ void stage_d2_tile(float* buf, int r0, int nrows, int tid) {
    const float4* src = (const float4*)(d2T + r0 * 112);
    unsigned d = su32(buf);
    int n = nrows * 28;
#pragma unroll
    for (int rep = 0; rep < 3; ++rep) {
        int i = tid + rep * THREADS;
        if (i < n) cpa16(d + i * 16, src + i);
    }
}

__global__ void __launch_bounds__(THREADS, 2)
seq2seq_gru_kernel(
    const float* __restrict__ enc_in,
    const float* __restrict__ enc_w1, const float* __restrict__ enc_b1,
    const float* __restrict__ enc_w2, const float* __restrict__ enc_b2,
    const float* __restrict__ enc_wl, const float* __restrict__ enc_bl,
    const float* __restrict__ w_ih,  const float* __restrict__ w_hh,
    const float* __restrict__ b_ih,  const float* __restrict__ b_hh,
    const float* __restrict__ dec_b1, const float* __restrict__ dec_b2,
    const float* __restrict__ dec_w3, const float* __restrict__ dec_b3,
    float* __restrict__ out)
{
    extern __shared__ float sm[];
    float* hbuf = sm + OFF_H;
    float* smY1 = sm + OFF_Y1;
    float* tbA  = sm + OFF_TA;
    float* tb0  = sm + OFF_T0;
    float* tb1  = sm + OFF_T1;
    float* gc   = sm + OFF_GC;
    float* cb1  = sm + OFF_B1;
    float* cb2  = sm + OFF_B2;
    float* w3s  = sm + OFF_W3;
    float* b3s  = sm + OFF_B3;
    float* din  = sm + OFF_DIN;
    float* ctab = sm + OFF_CT;
    float* stab = sm + OFF_ST;

    const int tid  = threadIdx.x;
    const int lane = tid & 31;
    const int w    = tid >> 5;          // 4 warps
    const int cta  = blockIdx.x;
    const float* inbase = enc_in + (size_t)cta * BT * LE;
    float* sig = hbuf;

    for (int idx = tid; idx < BT * LE; idx += THREADS) {
        int s = idx / LE, t = idx - s * LE;
        sig[s * HP + t] = inbase[idx];
    }
    if (tid < 100) {
        float u = (float)tid / 50.0f;
        ctab[tid] = cospif(u);
        stab[tid] = sinpif(u);
    }
    if (tid < BT) din[tid] = inbase[tid * LE + (LE - 1)];
    for (int j = tid; j < 200; j += THREADS) {
        gc[j * 8 + 0] = b_ih[j] + b_hh[j];
        gc[j * 8 + 1] = b_ih[HD + j] + b_hh[HD + j];
        gc[j * 8 + 2] = b_hh[2 * HD + j];
        gc[j * 8 + 3] = b_ih[2 * HD + j];
        gc[j * 8 + 4] = w_ih[j];
        gc[j * 8 + 5] = w_ih[HD + j];
        gc[j * 8 + 6] = w_ih[2 * HD + j];
        gc[j * 8 + 7] = 0.f;
    }
    if (tid < 100) cb1[tid] = dec_b1[tid];
    if (tid < 50)  { cb2[tid] = dec_b2[tid]; w3s[tid] = dec_w3[tid]; }
    if (tid == 0)  b3s[0] = dec_b3[0];
    __syncthreads();

    // DFT features
    for (int kk = 0; kk < 13; ++kk) {
        int k = w + 4 * kk;
        if (k < 51) {
#pragma unroll
            for (int p = 0; p < 2; ++p) {
                int s = lane + 32 * p;
                const float* xr = sig + s * HP;
                float re = 0.f, im = 0.f;
                int m = 0;
                for (int t = 0; t < LE; ++t) {
                    float xv = xr[t];
                    re += xv * ctab[m];
                    im -= xv * stab[m];
                    m += k; if (m >= 100) m -= 100;
                }
                re *= 0.01f; im *= 0.01f;
                if (k == 0 || k == 50) im = 0.0f;
                sig[s * HP + 100 + k] = sqrtf(re * re + im * im);
                sig[s * HP + 151 + k] = atan2f(im, re);
            }
        }
    }
    __syncthreads();

    // encoder L1 [202]->[100]
    {
        float* xbuf = smY1;
        for (int ii = 0; ii < 25; ++ii) {
            int i = w + 4 * ii;
            float b = enc_b1[i];
            const float* wr = enc_w1 + (size_t)i * SPD;
#pragma unroll
            for (int p = 0; p < 2; ++p) {
                int s = lane + 32 * p;
                xbuf[s * 100 + i] = lrelu(dotAB<101>(sig + s * HP, wr) + b);
            }
        }
        __syncthreads();
        // encoder L2 [100]->[202]
        for (int ii = 0; ii < 51; ++ii) {
            int i = w + 4 * ii;
            if (i < SPD) {
                float b = enc_b2[i];
                const float* wr = enc_w2 + (size_t)i * 100;
#pragma unroll
                for (int p = 0; p < 2; ++p) {
                    int s = lane + 32 * p;
                    sig[s * HP + i] = lrelu(dotAB<50>(xbuf + s * 100, wr) + b);
                }
            }
        }
        __syncthreads();
    }
    // encoder final [202]->[200] -> h0 in-place via tmp
    for (int half = 0; half < 2; ++half) {
        float* tmp = smY1;
        for (int ii = 0; ii < 50; ++ii) {
            int i = w + 4 * ii;
            int s = lane + 32 * half;
            tmp[lane * 200 + i] = dotAB<101>(sig + s * HP, enc_wl + (size_t)i * SPD) + enc_bl[i];
        }
        __syncthreads();
        for (int idx = tid; idx < 32 * 200; idx += THREADS) {
            int sp_ = idx / 200, i = idx - sp_ * 200;
            hbuf[(32 * half + sp_) * HP + i] = tmp[idx];
        }
        __syncthreads();
    }

    const int oct = lane >> 2;           // K-eighth
    const int sp  = lane & 3;
    const int sbase = w * 16 + sp * 4;   // lane owns samples sbase..sbase+3
    const int o0 = oct & 1, o1 = (oct >> 1) & 1, o2 = oct >> 2;
    const int q_lane = oct >> 1;
    const int s_gru = sbase + q_lane;
    const int s_dl1 = sbase + (oct & 3);
    const bool wr_y1 = (o2 == 0);

    // prefetch GRU tile 0 for step 0
    stage_gru_tile(tbA, 0, tid);
    CP_COMMIT();

    for (int t = 0; t < LD; ++t) {
        ull ha[4][14];
#pragma unroll
        for (int q = 0; q < 4; ++q) {
            float ta[28];
#pragma unroll
            for (int c = 0; c < 25; ++c)
                ta[c] = hbuf[(sbase + q) * HP + 25 * oct + c];
#pragma unroll
            for (int c = 25; c < 28; ++c) ta[c] = 0.f;
#pragma unroll
            for (int c = 0; c < 14; ++c) ha[q][c] = pk(ta[2 * c], ta[2 * c + 1]);
        }
        const float d_eff = din[s_gru];

        // deferred flush: stage2 + stage3 + gates + h RMW for round jb
        auto gru_flush = [&](float (&pu)[4][3], int jb) {
            float px[2][3], fin[3], zt, tt;
#pragma unroll
            for (int qh = 0; qh < 2; ++qh)
#pragma unroll
                for (int g = 0; g < 3; ++g) {
                    zt = o1 ? pu[qh * 2 + 0][g] : pu[qh * 2 + 1][g];
                    tt = __shfl_xor_sync(0xffffffffu, zt, 8);
                    px[qh][g] = (o1 ? pu[qh * 2 + 1][g] : pu[qh * 2 + 0][g]) + tt;
                }
#pragma unroll
            for (int g = 0; g < 3; ++g) {
                zt = o2 ? px[0][g] : px[1][g];
                tt = __shfl_xor_sync(0xffffffffu, zt, 16);
                fin[g] = (o2 ? px[1][g] : px[0][g]) + tt;
            }
            const int j_eff = jb + o0;
            float4 g0 = *(const float4*)(gc + j_eff * 8);
            float4 g1 = *(const float4*)(gc + j_eff * 8 + 4);
            float rG = sigm(fmaf(d_eff, g1.x, g0.x) + fin[0]);
            float zG = sigm(fmaf(d_eff, g1.y, g0.y) + fin[1]);
            float nG = tanh_f(fmaf(d_eff, g1.z, g0.w) + rG * (fin[2] + g0.z));
            const int hidx = s_gru * HP + j_eff;
            float ho = hbuf[hidx];
            hbuf[hidx] = (1.f - zG) * nG + zG * ho;
        };

        // ---- GRU: 25 tiles of 8 j (tile 0 prefetched) ----
        CP_WAIT0();
        __syncthreads();
        float pu[4][3];
        int pjb = -1;
#pragma unroll 1
        for (int k = 0; k < 25; ++k) {
            float* cur = (k & 1) ? smY1 : tbA;
            float* nxt = (k & 1) ? tbA : smY1;
            if (k + 1 < 25) { stage_gru_tile(nxt, k + 1, tid); }
            CP_COMMIT();
            const int j0 = k * 8;
            const float* cur_o = cur + oct * 28;
#pragma unroll 1
            for (int jp = 0; jp < 8; jp += 2) {
                const float* rowp = cur_o + jp * 3 * TP;
                const ulonglong2* W0 = (const ulonglong2*)(rowp + 0 * TP);
                const ulonglong2* W1 = (const ulonglong2*)(rowp + 1 * TP);
                const ulonglong2* W2 = (const ulonglong2*)(rowp + 2 * TP);
                const ulonglong2* W3 = (const ulonglong2*)(rowp + 3 * TP);
                const ulonglong2* W4 = (const ulonglong2*)(rowp + 4 * TP);
                const ulonglong2* W5 = (const ulonglong2*)(rowp + 5 * TP);
                ull acc[6][4];
#pragma unroll
                for (int r = 0; r < 6; ++r)
#pragma unroll
                    for (int q = 0; q < 4; ++q) acc[r][q] = 0ull;
#pragma unroll
                for (int c = 0; c < 7; ++c) {
                    ulonglong2 wv0 = W0[c], wv1 = W1[c], wv2 = W2[c];
                    ulonglong2 wv3 = W3[c], wv4 = W4[c], wv5 = W5[c];
#pragma unroll
                    for (int q = 0; q < 4; ++q) {
                        ull hx = ha[q][2 * c], hy = ha[q][2 * c + 1];
                        acc[0][q] = fma2(hx, wv0.x, acc[0][q]); acc[0][q] = fma2(hy, wv0.y, acc[0][q]);
                        acc[1][q] = fma2(hx, wv1.x, acc[1][q]); acc[1][q] = fma2(hy, wv1.y, acc[1][q]);
                        acc[2][q] = fma2(hx, wv2.x, acc[2][q]); acc[2][q] = fma2(hy, wv2.y, acc[2][q]);
                        acc[3][q] = fma2(hx, wv3.x, acc[3][q]); acc[3][q] = fma2(hy, wv3.y, acc[3][q]);
                        acc[4][q] = fma2(hx, wv4.x, acc[4][q]); acc[4][q] = fma2(hy, wv4.y, acc[4][q]);
                        acc[5][q] = fma2(hx, wv5.x, acc[5][q]); acc[5][q] = fma2(hy, wv5.y, acc[5][q]);
                    }
                }
                float v[8][3];
#pragma unroll
                for (int q = 0; q < 4; ++q)
#pragma unroll
                    for (int g = 0; g < 3; ++g) {
                        v[q * 2 + 0][g] = red2(acc[g][q]);
                        v[q * 2 + 1][g] = red2(acc[3 + g][q]);
                    }
                // flush PREVIOUS pair-round (stage2+3+gates+RMW)
                if (pjb >= 0) gru_flush(pu, pjb);
                // stage1 only for CURRENT round; carry pre-stage2
                {
                    float zt, tt;
#pragma unroll
                    for (int q = 0; q < 4; ++q)
#pragma unroll
                        for (int g = 0; g < 3; ++g) {
                            zt = o0 ? v[q * 2 + 0][g] : v[q * 2 + 1][g];
                            tt = __shfl_xor_sync(0xffffffffu, zt, 4);
                            pu[q][g] = (o0 ? v[q * 2 + 1][g] : v[q * 2 + 0][g]) + tt;
                        }
                }
                pjb = j0 + jp;
            }
            CP_WAIT0();
            __syncthreads();
        }
        // prefetch dec L1 tile 0; hidden behind final flush + restash
        stage_d1_tile(tb0, 0, 12, tid);
        CP_COMMIT();
        gru_flush(pu, pjb);
        __syncwarp();

        // ---- dec L1 [200]->[100] ----
#pragma unroll
        for (int q = 0; q < 4; ++q) {
            float ta[28];
#pragma unroll
            for (int c = 0; c < 25; ++c)
                ta[c] = hbuf[(sbase + q) * HP + 25 * oct + c];
#pragma unroll
            for (int c = 25; c < 28; ++c) ta[c] = 0.f;
#pragma unroll
            for (int c = 0; c < 14; ++c) ha[q][c] = pk(ta[2 * c], ta[2 * c + 1]);
        }
        CP_WAIT0();
        __syncthreads();
        float pq0 = 0.f, pq1 = 0.f;
        int prow = -1;
#pragma unroll 1
        for (int k = 0; k < 9; ++k) {
            float* cur = (k & 1) ? tb1 : tb0;
            float* nxt = (k & 1) ? tb0 : tb1;
            if (k + 1 < 9) {
                int r0n = (k + 1) * 12;
                stage_d1_tile(nxt, r0n, min(12, 100 - r0n), tid);
            } else {
                stage_d2_tile(nxt, 0, 12, tid);   // dec L2 tile 0 into tb1
            }
            CP_COMMIT();
            const int r0 = k * 12;
            const int nr = min(12, 100 - r0);
            const float* cur_o = cur + oct * 28;
#pragma unroll 4
            for (int lr = 0; lr < nr; ++lr) {
                const int row = r0 + lr;
                const ulonglong2* W2 = (const ulonglong2*)(cur_o + lr * TP);
                ull a0 = 0, a1 = 0, a2 = 0, a3 = 0;
#pragma unroll
                for (int c = 0; c < 7; ++c) {
                    ulonglong2 wv = W2[c];
                    a0 = fma2(ha[0][2 * c], wv.x, a0); a0 = fma2(ha[0][2 * c + 1], wv.y, a0);
                    a1 = fma2(ha[1][2 * c], wv.x, a1); a1 = fma2(ha[1][2 * c + 1], wv.y, a1);
                    a2 = fma2(ha[2][2 * c], wv.x, a2); a2 = fma2(ha[2][2 * c + 1], wv.y, a2);
                    a3 = fma2(ha[3][2 * c], wv.x, a3); a3 = fma2(ha[3][2 * c + 1], wv.y, a3);
                }
                float v0 = red2(a0), v1 = red2(a1), v2 = red2(a2), v3 = red2(a3);
                // flush previous row: stage2 + stage3 + write
                if (prow >= 0) {
                    float zt = o1 ? pq0 : pq1;
                    float tt = __shfl_xor_sync(0xffffffffu, zt, 8);
                    float xx = (o1 ? pq1 : pq0) + tt;
                    float fv = xx + __shfl_xor_sync(0xffffffffu, xx, 16);
                    if (wr_y1)
                        smY1[s_dl1 * Y1P + prow] = lrelu(fv + cb1[prow]);
                }
                float zt, tt;
                zt = o0 ? v0 : v1;
                tt = __shfl_xor_sync(0xffffffffu, zt, 4);
                pq0 = (o0 ? v1 : v0) + tt;
                zt = o0 ? v2 : v3;
                tt = __shfl_xor_sync(0xffffffffu, zt, 4);
                pq1 = (o0 ? v3 : v2) + tt;
                prow = row;
            }
            CP_WAIT0();
            __syncthreads();
        }
        {
            float zt = o1 ? pq0 : pq1;
            float tt = __shfl_xor_sync(0xffffffffu, zt, 8);
            float xx = (o1 ? pq1 : pq0) + tt;
            float fv = xx + __shfl_xor_sync(0xffffffffu, xx, 16);
            if (wr_y1)
                smY1[s_dl1 * Y1P + prow] = lrelu(fv + cb1[prow]);
        }
        __syncwarp();

        // ---- dec L2 [100]->[50]; tile 0 already in tb1 ----
        const int q2 = lane >> 3;
        const int s2 = lane & 7;
        const int sampA = w * 16 + s2;
        const int sampB = sampA + 8;
        ull ya[2][14];
#pragma unroll
        for (int v = 0; v < 2; ++v) {
            int samp = v ? sampB : sampA;
            float tv[28];
#pragma unroll
            for (int c = 0; c < 25; ++c) tv[c] = smY1[samp * Y1P + 25 * q2 + c];
#pragma unroll
            for (int c = 25; c < 28; ++c) tv[c] = 0.f;
#pragma unroll
            for (int c = 0; c < 14; ++c) ya[v][c] = pk(tv[2 * c], tv[2 * c + 1]);
        }
        CP_WAIT0();
        __syncthreads();   // y1 stashes done before y2 overlay writes
        float* smY2 = smY1;
        const int q2b0 = q2 & 1;
        const int s_dl2 = q2b0 ? sampB : sampA;
        const bool wr_y2 = (q2 < 2);
        float pv0 = 0.f, pv1 = 0.f;
        int prow2 = -1;
#pragma unroll 1
        for (int k = 0; k < 5; ++k) {
            float* cur = (k & 1) ? tb0 : tb1;   // parity: tile0 in tb1
            float* nxt = (k & 1) ? tb1 : tb0;
            if (k + 1 < 5) {
                int r0n = (k + 1) * 12;
                stage_d2_tile(nxt, r0n, min(12, 50 - r0n), tid);
            }
            CP_COMMIT();
            const int r0 = k * 12;
            const int nr = min(12, 50 - r0);
            const float* cur_q = cur + q2 * 28;
#pragma unroll 4
            for (int lr = 0; lr < nr; ++lr) {
                const int row = r0 + lr;
                const ulonglong2* W2 = (const ulonglong2*)(cur_q + lr * TP2);
                ull a0 = 0, a1 = 0;
#pragma unroll
                for (int c = 0; c < 7; ++c) {
                    ulonglong2 wv = W2[c];
                    a0 = fma2(ya[0][2 * c], wv.x, a0); a0 = fma2(ya[0][2 * c + 1], wv.y, a0);
                    a1 = fma2(ya[1][2 * c], wv.x, a1); a1 = fma2(ya[1][2 * c + 1], wv.y, a1);
                }
                float v0 = red2(a0), v1 = red2(a1);
                // flush previous row: stage1 + stage2 + write
                if (prow2 >= 0) {
                    float zt = q2b0 ? pv0 : pv1;
                    float tt = __shfl_xor_sync(0xffffffffu, zt, 8);
                    float uu = (q2b0 ? pv1 : pv0) + tt;
                    float fu = uu + __shfl_xor_sync(0xffffffffu, uu, 16);
                    if (wr_y2)
                        smY2[s_dl2 * Y2P + prow2] = lrelu(fu + cb2[prow2]);
                }
                pv0 = v0; pv1 = v1;
                prow2 = row;
            }
            CP_WAIT0();
            __syncthreads();
        }
        {
            float zt = q2b0 ? pv0 : pv1;
            float tt = __shfl_xor_sync(0xffffffffu, zt, 8);
            float uu = (q2b0 ? pv1 : pv0) + tt;
            float fu = uu + __shfl_xor_sync(0xffffffffu, uu, 16);
            if (wr_y2)
                smY2[s_dl2 * Y2P + prow2] = lrelu(fu + cb2[prow2]);
        }
        // prefetch next step's GRU tile 0
        if (t + 1 < LD) {
            stage_gru_tile(tbA, 0, tid);
            CP_COMMIT();
        }
        __syncthreads();

        // ---- dec L3 + feedback ----
        if (tid < BT) {
            float acc = b3s[0];
            for (int c = 0; c < 50; ++c)
                acc += smY2[tid * Y2P + c] * w3s[c];
            out[((size_t)(cta * BT + tid)) * LD + t] = acc;
            din[tid] = acc;
        }
        __syncthreads();
    }
}

extern "C" void kernel_launch(void* const* d_in, const int* in_sizes, int n_in,
                              void* d_out, int out_size) {
    const float* enc_in = (const float*)d_in[0];
    const float* enc_w1 = (const float*)d_in[1];
    const float* enc_b1 = (const float*)d_in[2];
    const float* enc_w2 = (const float*)d_in[3];
    const float* enc_b2 = (const float*)d_in[4];
    const float* enc_wl = (const float*)d_in[5];
    const float* enc_bl = (const float*)d_in[6];
    const float* w_ih   = (const float*)d_in[7];
    const float* w_hh   = (const float*)d_in[8];
    const float* b_ih   = (const float*)d_in[9];
    const float* b_hh   = (const float*)d_in[10];
    const float* dec_w1 = (const float*)d_in[11];
    const float* dec_b1 = (const float*)d_in[12];
    const float* dec_w2 = (const float*)d_in[13];
    const float* dec_b2 = (const float*)d_in[14];
    const float* dec_w3 = (const float*)d_in[15];
    const float* dec_b3 = (const float*)d_in[16];
    float* out = (float*)d_out;

    const int prep_total = 25 * 24 * 224 + 100 * 224 + 50 * 112;
    prep_kernel<<<(prep_total + 255) / 256, 256>>>(w_hh, dec_w1, dec_w2);

    cudaFuncSetAttribute(seq2seq_gru_kernel,
                         cudaFuncAttributeMaxDynamicSharedMemorySize, SMEM_BYTES);
    seq2seq_gru_kernel<<<NS / BT, THREADS, SMEM_BYTES>>>(
        enc_in, enc_w1, enc_b1, enc_w2, enc_b2, enc_wl, enc_bl,
        w_ih, w_hh, b_ih, b_hh,
        dec_b1, dec_b2, dec_w3, dec_b3, out);
}